// round 1
// baseline (speedup 1.0000x reference)
#include <cuda_runtime.h>
#include <cuda_bf16.h>
#include <math.h>

// Problem dims
#define BB 64
#define SS 50
#define EE 512
#define HH 1024
#define VTS 32000
#define NSTEP 49
#define MPROJ (NSTEP*BB)   /* 3136 */
#define G4H 4096
#define KSPLIT 8
#define KCHUNK 192         /* 1536/8 */

typedef unsigned long long ull;

// ---------- packed f32x2 helpers (FFMA2: 2 FMA per instruction) ----------
__device__ __forceinline__ ull dup2(float x){
    ull r; asm("mov.b64 %0, {%1, %1};" : "=l"(r) : "f"(x)); return r;
}
__device__ __forceinline__ void ffma2(ull &d, ull a, ull b){
    asm("fma.rn.f32x2 %0, %1, %2, %0;" : "+l"(d) : "l"(a), "l"(b));
}
__device__ __forceinline__ float2 unpk(ull v){
    float2 f; asm("mov.b64 {%0, %1}, %2;" : "=f"(f.x), "=f"(f.y) : "l"(v)); return f;
}

// ---------- scratch (static device memory; no runtime allocation) ----------
__device__ float g_enc_out[BB*SS*EE];          // (B*S, E)
__device__ float g_avg[BB*EE];
__device__ float g_ctx[BB*EE];
__device__ float g_h[BB*HH];
__device__ float g_c[BB*HH];
__device__ float g_gconst[BB*G4H];
__device__ float g_part[KSPLIT*BB*G4H];        // split-K partials for gates
__device__ float g_Hall[NSTEP*BB*HH];          // all hidden states (rows = t*64+b)

// ============================================================
// Encoder GEMM: enc_out[r, n] = sum_k A[r,k]*cat_W[n,k] + cat_b[n]
// A[r,k] = k<512 ? enc_emb[src[r], k] : pos_emb[pos[r], k-512]
// M=3200 (25 tiles of 128), N=512 (4 tiles of 128), K=1024
// 256 threads, per-thread 8m x 8n, FFMA2 paired along n
// ============================================================
__global__ __launch_bounds__(256)
void enc_gemm(const int* __restrict__ src, const int* __restrict__ pos,
              const float* __restrict__ enc_emb, const float* __restrict__ pos_emb,
              const float* __restrict__ cat_W, const float* __restrict__ cat_b)
{
    __shared__ __align__(16) float As[128*20];   // As[m*20 + k]
    __shared__ __align__(16) float Bs[16*132];   // Bs[k*132 + n]
    const int m0 = blockIdx.x * 128;
    const int n0 = blockIdx.y * 128;
    const int tid = threadIdx.x;
    const int tx = tid & 15, ty = tid >> 4;

    ull acc[8][2][2];
    #pragma unroll
    for (int i=0;i<8;i++)
        #pragma unroll
        for (int q=0;q<2;q++){ acc[i][q][0]=0ull; acc[i][q][1]=0ull; }

    for (int kt = 0; kt < 1024; kt += 16){
        #pragma unroll
        for (int l=0;l<2;l++){   // A tile: 128 rows x 16 k (512 float4)
            int f4 = tid + 256*l;
            int row = f4 >> 2, k4 = (f4 & 3) << 2;
            int kg = kt + k4;
            int r = m0 + row;
            float4 v;
            if (kg < 512) v = *(const float4*)(enc_emb + (size_t)src[r]*512 + kg);
            else          v = *(const float4*)(pos_emb + (size_t)pos[r]*512 + (kg - 512));
            *(float4*)(As + row*20 + k4) = v;
        }
        #pragma unroll
        for (int l=0;l<2;l++){   // B tile: 128 n-rows x 16 k, transposed store
            int f4 = tid + 256*l;
            int row = f4 >> 2, k4 = (f4 & 3) << 2;
            float4 v = *(const float4*)(cat_W + (size_t)(n0+row)*1024 + kt + k4);
            Bs[(k4+0)*132 + row] = v.x;
            Bs[(k4+1)*132 + row] = v.y;
            Bs[(k4+2)*132 + row] = v.z;
            Bs[(k4+3)*132 + row] = v.w;
        }
        __syncthreads();
        #pragma unroll
        for (int kq=0;kq<4;kq++){
            float4 av[8];
            #pragma unroll
            for (int i=0;i<8;i++) av[i] = *(const float4*)(As + (ty*8+i)*20 + kq*4);
            #pragma unroll
            for (int kk=0;kk<4;kk++){
                ull a2[8];
                #pragma unroll
                for (int i=0;i<8;i++){
                    float a = (kk==0)?av[i].x:(kk==1)?av[i].y:(kk==2)?av[i].z:av[i].w;
                    a2[i] = dup2(a);
                }
                const int k = kq*4+kk;
                #pragma unroll
                for (int q=0;q<2;q++){
                    ulonglong2 bv = *(const ulonglong2*)(Bs + k*132 + tx*4 + q*64);
                    #pragma unroll
                    for (int i=0;i<8;i++){ ffma2(acc[i][q][0], a2[i], bv.x);
                                           ffma2(acc[i][q][1], a2[i], bv.y); }
                }
            }
        }
        __syncthreads();
    }
    #pragma unroll
    for (int i=0;i<8;i++){
        int gm = m0 + ty*8 + i;
        #pragma unroll
        for (int q=0;q<2;q++){
            int gn = n0 + tx*4 + q*64;
            float2 p0 = unpk(acc[i][q][0]);
            float2 p1 = unpk(acc[i][q][1]);
            float4 bb = *(const float4*)(cat_b + gn);
            *(float4*)(g_enc_out + (size_t)gm*512 + gn) =
                make_float4(p0.x+bb.x, p0.y+bb.y, p1.x+bb.z, p1.y+bb.w);
        }
    }
}

// ============================================================
// avg over S
// ============================================================
__global__ void avg_kernel()
{
    int b = blockIdx.x, e = threadIdx.x;   // 64 blocks x 512 threads
    float s = 0.f;
    #pragma unroll 5
    for (int si=0; si<SS; si++) s += g_enc_out[(b*SS+si)*EE + e];
    g_avg[b*EE + e] = s * (1.0f/50.0f);
}

// ============================================================
// h0 = relu(avg @ scale_W^T + scale_b); init h and c
// ============================================================
__global__ void h0_kernel(const float* __restrict__ scale_W, const float* __restrict__ scale_b)
{
    int gid = blockIdx.x*blockDim.x + threadIdx.x;  // 65536
    int b = gid >> 10, h = gid & 1023;
    const float4* a = (const float4*)(g_avg + b*EE);
    const float4* w = (const float4*)(scale_W + (size_t)h*EE);
    float s = 0.f;
    #pragma unroll 8
    for (int i=0;i<128;i++){
        float4 av=a[i], wv=w[i];
        s += av.x*wv.x + av.y*wv.y + av.z*wv.z + av.w*wv.w;
    }
    float v = fmaxf(s + scale_b[h], 0.f);
    g_h[gid] = v; g_c[gid] = v;
}

// ============================================================
// Attention (loop-invariant!): scores from enc-part only (softmax shift-inv),
// mask PAD=0, renormalize, ctx[b] = sum_s aw[s]*enc_out[b,s,:]
// ============================================================
__global__ void attn_kernel(const float* __restrict__ attn_W, const int* __restrict__ src)
{
    int b = blockIdx.x, tid = threadIdx.x;
    __shared__ float sc[56];
    __shared__ float aw[56];
    int w = tid >> 5, lane = tid & 31;
    for (int s = w; s < SS; s += 8){
        const float* row = g_enc_out + (size_t)(b*SS+s)*EE;
        float a = 0.f;
        for (int e = lane; e < EE; e += 32) a += row[e]*attn_W[e];
        #pragma unroll
        for (int o=16;o>0;o>>=1) a += __shfl_xor_sync(0xffffffffu, a, o);
        if (lane==0) sc[s] = a;
    }
    __syncthreads();
    if (tid == 0){
        float mx = -1e30f;
        for (int s=0;s<SS;s++) mx = fmaxf(mx, sc[s]);
        float tot = 0.f;
        for (int s=0;s<SS;s++){
            float e = (src[b*SS+s]==0) ? 0.f : expf(sc[s]-mx);
            aw[s] = e; tot += e;
        }
        float inv = 1.f/tot;
        for (int s=0;s<SS;s++) aw[s] *= inv;
    }
    __syncthreads();
    for (int e = tid; e < EE; e += blockDim.x){
        float a = 0.f;
        #pragma unroll 5
        for (int s=0;s<SS;s++) a += aw[s]*g_enc_out[(size_t)(b*SS+s)*EE + e];
        g_ctx[b*EE + e] = a;
    }
}

// ============================================================
// gconst[b,j] = ctx[b] . W_ih[j, 512:1024] + b_ih[j] + b_hh[j]
// ============================================================
__global__ void gconst_kernel(const float* __restrict__ W_ih,
                              const float* __restrict__ b_ih, const float* __restrict__ b_hh)
{
    int gid = blockIdx.x*blockDim.x + threadIdx.x;  // 262144
    int b = gid >> 12, j = gid & 4095;
    const float4* c4 = (const float4*)(g_ctx + b*EE);
    const float4* w4 = (const float4*)(W_ih + (size_t)j*1024 + 512);
    float s = 0.f;
    #pragma unroll 8
    for (int i=0;i<128;i++){
        float4 cv=c4[i], wv=w4[i];
        s += cv.x*wv.x + cv.y*wv.y + cv.z*wv.z + cv.w*wv.w;
    }
    g_gconst[gid] = s + b_ih[j] + b_hh[j];
}

// ============================================================
// Per-step gates GEMM (split-K, 8 splits of 192):
// part[ks][b][j] = sum_{k in chunk} A[b,k] * W[j,k]
// A[b,k] = k<512 ? dec_emb[tok[b],k] : h[b,k-512]
// W[j,k] = k<512 ? W_ih[j,k]        : W_hh[j,k-512]
// grid(32 n-tiles, 8 ksplits), 128 threads, per-thread 8m x 8n
// ============================================================
__global__ __launch_bounds__(128)
void gates_gemm(const int* __restrict__ tgt, int t,
                const float* __restrict__ dec_emb,
                const float* __restrict__ W_ih, const float* __restrict__ W_hh)
{
    __shared__ __align__(16) float As[64*20];
    __shared__ __align__(16) float Bs[16*132];
    const int n0 = blockIdx.x * 128;
    const int kbase = blockIdx.y * KCHUNK;
    const int tid = threadIdx.x;
    const int tx = tid & 15, ty = tid >> 4;   // ty in [0,8)

    ull acc[8][2][2];
    #pragma unroll
    for (int i=0;i<8;i++)
        #pragma unroll
        for (int q=0;q<2;q++){ acc[i][q][0]=0ull; acc[i][q][1]=0ull; }

    for (int kt = 0; kt < KCHUNK; kt += 16){
        const int kg0 = kbase + kt;
        #pragma unroll
        for (int l=0;l<2;l++){   // A tile: 64 rows x 16 k (256 float4)
            int f4 = tid + 128*l;
            int row = f4 >> 2, k4 = (f4 & 3) << 2;
            int kg = kg0 + k4;
            float4 v;
            if (kg < 512){
                int tok = tgt[row*50 + t];
                v = *(const float4*)(dec_emb + (size_t)tok*512 + kg);
            } else {
                v = *(const float4*)(g_h + row*1024 + (kg-512));
            }
            *(float4*)(As + row*20 + k4) = v;
        }
        #pragma unroll
        for (int l=0;l<4;l++){   // B tile: 128 rows x 16 k (512 float4)
            int f4 = tid + 128*l;
            int row = f4 >> 2, k4 = (f4 & 3) << 2;
            int kg = kg0 + k4;
            const float* sp = (kg < 512) ? (W_ih + (size_t)(n0+row)*1024 + kg)
                                         : (W_hh + (size_t)(n0+row)*1024 + (kg-512));
            float4 v = *(const float4*)sp;
            Bs[(k4+0)*132 + row] = v.x;
            Bs[(k4+1)*132 + row] = v.y;
            Bs[(k4+2)*132 + row] = v.z;
            Bs[(k4+3)*132 + row] = v.w;
        }
        __syncthreads();
        #pragma unroll
        for (int kq=0;kq<4;kq++){
            float4 av[8];
            #pragma unroll
            for (int i=0;i<8;i++) av[i] = *(const float4*)(As + (ty*8+i)*20 + kq*4);
            #pragma unroll
            for (int kk=0;kk<4;kk++){
                ull a2[8];
                #pragma unroll
                for (int i=0;i<8;i++){
                    float a = (kk==0)?av[i].x:(kk==1)?av[i].y:(kk==2)?av[i].z:av[i].w;
                    a2[i] = dup2(a);
                }
                const int k = kq*4+kk;
                #pragma unroll
                for (int q=0;q<2;q++){
                    ulonglong2 bv = *(const ulonglong2*)(Bs + k*132 + tx*4 + q*64);
                    #pragma unroll
                    for (int i=0;i<8;i++){ ffma2(acc[i][q][0], a2[i], bv.x);
                                           ffma2(acc[i][q][1], a2[i], bv.y); }
                }
            }
        }
        __syncthreads();
    }
    float* outp = g_part + (size_t)blockIdx.y*(BB*G4H);
    #pragma unroll
    for (int i=0;i<8;i++){
        int m = ty*8 + i;
        #pragma unroll
        for (int q=0;q<2;q++){
            int n = n0 + tx*4 + q*64;
            float2 p0 = unpk(acc[i][q][0]);
            float2 p1 = unpk(acc[i][q][1]);
            *(float4*)(outp + (size_t)m*G4H + n) = make_float4(p0.x, p0.y, p1.x, p1.y);
        }
    }
}

// ============================================================
// LSTM pointwise: sum split-K partials + gconst, gate, update h/c, record h
// ============================================================
__global__ void lstm_pw(int t)
{
    int gid = blockIdx.x*blockDim.x + threadIdx.x;   // 65536
    int b = gid >> 10, h = gid & 1023;
    int base = b*G4H;
    float gi = g_gconst[base + h];
    float gf = g_gconst[base + 1024 + h];
    float gg = g_gconst[base + 2048 + h];
    float go = g_gconst[base + 3072 + h];
    #pragma unroll
    for (int s=0;s<KSPLIT;s++){
        const float* p = g_part + (size_t)s*(BB*G4H) + base;
        gi += p[h]; gf += p[1024+h]; gg += p[2048+h]; go += p[3072+h];
    }
    float c  = g_c[gid];
    float ii = 1.f/(1.f+expf(-gi));
    float ff = 1.f/(1.f+expf(-gf));
    float oo = 1.f/(1.f+expf(-go));
    float gt = tanhf(gg);
    float cn = ff*c + ii*gt;
    float hn = oo*tanhf(cn);
    g_c[gid] = cn; g_h[gid] = hn;
    g_Hall[(size_t)t*(BB*HH) + gid] = hn;
}

// ============================================================
// Projection GEMM: out[r, v] = Hall[r,:] . proj_W[v,:] + proj_b[v]
// M=3136 (25 tiles of 128, guarded), N=32000 (125 tiles of 256), K=1024
// 256 threads, per-thread 8m x 16n, FFMA2 paired along n
// ============================================================
__global__ __launch_bounds__(256, 1)
void proj_gemm(float* __restrict__ out,
               const float* __restrict__ W, const float* __restrict__ bias)
{
    __shared__ __align__(16) float As[128*20];   // As[m*20 + k]
    __shared__ __align__(16) float Bs[16*260];   // Bs[k*260 + n]
    const int m0 = blockIdx.x * 128;
    const int n0 = blockIdx.y * 256;
    const int tid = threadIdx.x;
    const int tx = tid & 15, ty = tid >> 4;

    ull acc[8][4][2];
    #pragma unroll
    for (int i=0;i<8;i++)
        #pragma unroll
        for (int q=0;q<4;q++){ acc[i][q][0]=0ull; acc[i][q][1]=0ull; }

    for (int kt = 0; kt < 1024; kt += 16){
        #pragma unroll
        for (int l=0;l<2;l++){   // A tile: 128 rows x 16 k
            int f4 = tid + 256*l;
            int row = f4 >> 2, k4 = (f4 & 3) << 2;
            int gm = m0 + row;
            float4 v = make_float4(0.f,0.f,0.f,0.f);
            if (gm < MPROJ) v = *(const float4*)(g_Hall + (size_t)gm*1024 + kt + k4);
            *(float4*)(As + row*20 + k4) = v;
        }
        #pragma unroll
        for (int l=0;l<4;l++){   // B tile: 256 rows x 16 k, transposed store
            int f4 = tid + 256*l;
            int row = f4 >> 2, k4 = (f4 & 3) << 2;
            float4 v = *(const float4*)(W + (size_t)(n0+row)*1024 + kt + k4);
            Bs[(k4+0)*260 + row] = v.x;
            Bs[(k4+1)*260 + row] = v.y;
            Bs[(k4+2)*260 + row] = v.z;
            Bs[(k4+3)*260 + row] = v.w;
        }
        __syncthreads();
        #pragma unroll
        for (int kq=0;kq<4;kq++){
            float4 av[8];
            #pragma unroll
            for (int i=0;i<8;i++) av[i] = *(const float4*)(As + (ty*8+i)*20 + kq*4);
            #pragma unroll
            for (int kk=0;kk<4;kk++){
                ull a2[8];
                #pragma unroll
                for (int i=0;i<8;i++){
                    float a = (kk==0)?av[i].x:(kk==1)?av[i].y:(kk==2)?av[i].z:av[i].w;
                    a2[i] = dup2(a);
                }
                const int k = kq*4+kk;
                #pragma unroll
                for (int q=0;q<4;q++){
                    ulonglong2 bv = *(const ulonglong2*)(Bs + k*260 + tx*4 + q*64);
                    #pragma unroll
                    for (int i=0;i<8;i++){ ffma2(acc[i][q][0], a2[i], bv.x);
                                           ffma2(acc[i][q][1], a2[i], bv.y); }
                }
            }
        }
        __syncthreads();
    }
    #pragma unroll
    for (int i=0;i<8;i++){
        int gm = m0 + ty*8 + i;
        if (gm >= MPROJ) continue;
        #pragma unroll
        for (int q=0;q<4;q++){
            int gn = n0 + tx*4 + q*64;
            float2 p0 = unpk(acc[i][q][0]);
            float2 p1 = unpk(acc[i][q][1]);
            float4 bb = *(const float4*)(bias + gn);
            *(float4*)(out + (size_t)gm*VTS + gn) =
                make_float4(p0.x+bb.x, p0.y+bb.y, p1.x+bb.z, p1.y+bb.w);
        }
    }
}

// ============================================================
extern "C" void kernel_launch(void* const* d_in, const int* in_sizes, int n_in,
                              void* d_out, int out_size)
{
    const int*   src      = (const int*)  d_in[0];
    /* d_in[1] = source_lengths (unused by reference) */
    const int*   pos      = (const int*)  d_in[2];
    const int*   tgt      = (const int*)  d_in[3];
    const float* enc_emb  = (const float*)d_in[4];
    const float* pos_emb  = (const float*)d_in[5];
    const float* cat_W    = (const float*)d_in[6];
    const float* cat_b    = (const float*)d_in[7];
    const float* scale_W  = (const float*)d_in[8];
    const float* scale_b  = (const float*)d_in[9];
    const float* dec_emb  = (const float*)d_in[10];
    const float* attn_W   = (const float*)d_in[11];
    /* d_in[12] = attn_b: constant shift, cancelled by softmax */
    const float* W_ih     = (const float*)d_in[13];
    const float* W_hh     = (const float*)d_in[14];
    const float* b_ih     = (const float*)d_in[15];
    const float* b_hh     = (const float*)d_in[16];
    const float* proj_W   = (const float*)d_in[17];
    const float* proj_b   = (const float*)d_in[18];
    float* out = (float*)d_out;

    // Encoder
    enc_gemm<<<dim3(25,4), 256>>>(src, pos, enc_emb, pos_emb, cat_W, cat_b);
    avg_kernel<<<64, 512>>>();
    h0_kernel<<<256, 256>>>(scale_W, scale_b);

    // Loop-invariant attention context + constant gate contribution
    attn_kernel<<<64, 256>>>(attn_W, src);
    gconst_kernel<<<1024, 256>>>(W_ih, b_ih, b_hh);

    // Recurrence: 49 sequential steps (gates split-K GEMM + pointwise LSTM)
    for (int t = 0; t < NSTEP; t++){
        gates_gemm<<<dim3(32, KSPLIT), 128>>>(tgt, t, dec_emb, W_ih, W_hh);
        lstm_pw<<<256, 256>>>(t);
    }

    // One batched projection over all 49 steps
    proj_gemm<<<dim3(25,125), 256>>>(out, proj_W, proj_b);
}

// round 3
// speedup vs baseline: 1.4757x; 1.4757x over previous
#include <cuda_runtime.h>
#include <cuda_bf16.h>
#include <math.h>
#include <stdint.h>

// Problem dims
#define BB 64
#define SS 50
#define EE 512
#define HH 1024
#define VTS 32000
#define NSTEP 49
#define MPROJ (NSTEP*BB)   /* 3136 */
#define MPAD  3200
#define G4H 4096
#define KSPLIT 8
#define KCHUNK 128         /* 1024/8 */
#define KCAT 3072          /* 3-term concat K */

typedef unsigned long long ull;

// ---------- packed f32x2 helpers ----------
__device__ __forceinline__ ull dup2(float x){
    ull r; asm("mov.b64 %0, {%1, %1};" : "=l"(r) : "f"(x)); return r;
}
__device__ __forceinline__ void ffma2(ull &d, ull a, ull b){
    asm("fma.rn.f32x2 %0, %1, %2, %0;" : "+l"(d) : "l"(a), "l"(b));
}
__device__ __forceinline__ float2 unpk(ull v){
    float2 f; asm("mov.b64 {%0, %1}, %2;" : "=f"(f.x), "=f"(f.y) : "l"(v)); return f;
}

// ---------- baseline-PTX tensor helpers (no 'a'-target features) ----------
__device__ __forceinline__ uint32_t smem_u32(const void* p){
    uint32_t a;
    asm("{ .reg .u64 t; cvta.to.shared.u64 t, %1; cvt.u32.u64 %0, t; }" : "=r"(a) : "l"(p));
    return a;
}
__device__ __forceinline__ void cpasync16(uint32_t dst, const void* src){
    asm volatile("cp.async.cg.shared.global [%0], [%1], 16;" :: "r"(dst), "l"(src));
}
__device__ __forceinline__ void cp_commit(){
    asm volatile("cp.async.commit_group;");
}
__device__ __forceinline__ void ldm4(uint32_t* r, uint32_t a){
    asm volatile("ldmatrix.sync.aligned.m8n8.x4.shared.b16 {%0,%1,%2,%3}, [%4];"
        : "=r"(r[0]), "=r"(r[1]), "=r"(r[2]), "=r"(r[3]) : "r"(a));
}
__device__ __forceinline__ void mma16816(float* c, const uint32_t* a, uint32_t b0, uint32_t b1){
    asm volatile("mma.sync.aligned.m16n8k16.row.col.f32.bf16.bf16.f32 "
        "{%0,%1,%2,%3}, {%4,%5,%6,%7}, {%8,%9}, {%0,%1,%2,%3};"
        : "+f"(c[0]), "+f"(c[1]), "+f"(c[2]), "+f"(c[3])
        : "r"(a[0]), "r"(a[1]), "r"(a[2]), "r"(a[3]), "r"(b0), "r"(b1));
}

// ---------- scratch ----------
__device__ float g_enc_out[BB*SS*EE];
__device__ float g_avg[BB*EE];
__device__ float g_ctx[BB*EE];
__device__ float g_h[BB*HH];
__device__ float g_c[BB*HH];
__device__ float g_gconst[BB*G4H];
__device__ float g_part[KSPLIT*BB*G4H];
__device__ float g_pre[MPAD*G4H];                    // per-step const gate input
__device__ __nv_bfloat16 g_Acat[(size_t)MPAD*KCAT];  // [Ah|Ah|Al] rows (zero beyond 3136)
__device__ __nv_bfloat16 g_Bcat[(size_t)VTS*KCAT];   // [Bh|Bl|Bh] rows

// ============================================================
// Encoder GEMM (fp32 FFMA2) — unchanged from round 1
// ============================================================
__global__ __launch_bounds__(256)
void enc_gemm(const int* __restrict__ src, const int* __restrict__ pos,
              const float* __restrict__ enc_emb, const float* __restrict__ pos_emb,
              const float* __restrict__ cat_W, const float* __restrict__ cat_b)
{
    __shared__ __align__(16) float As[128*20];
    __shared__ __align__(16) float Bs[16*132];
    const int m0 = blockIdx.x * 128;
    const int n0 = blockIdx.y * 128;
    const int tid = threadIdx.x;
    const int tx = tid & 15, ty = tid >> 4;

    ull acc[8][2][2];
    #pragma unroll
    for (int i=0;i<8;i++)
        #pragma unroll
        for (int q=0;q<2;q++){ acc[i][q][0]=0ull; acc[i][q][1]=0ull; }

    for (int kt = 0; kt < 1024; kt += 16){
        #pragma unroll
        for (int l=0;l<2;l++){
            int f4 = tid + 256*l;
            int row = f4 >> 2, k4 = (f4 & 3) << 2;
            int kg = kt + k4;
            int r = m0 + row;
            float4 v;
            if (kg < 512) v = *(const float4*)(enc_emb + (size_t)src[r]*512 + kg);
            else          v = *(const float4*)(pos_emb + (size_t)pos[r]*512 + (kg - 512));
            *(float4*)(As + row*20 + k4) = v;
        }
        #pragma unroll
        for (int l=0;l<2;l++){
            int f4 = tid + 256*l;
            int row = f4 >> 2, k4 = (f4 & 3) << 2;
            float4 v = *(const float4*)(cat_W + (size_t)(n0+row)*1024 + kt + k4);
            Bs[(k4+0)*132 + row] = v.x;
            Bs[(k4+1)*132 + row] = v.y;
            Bs[(k4+2)*132 + row] = v.z;
            Bs[(k4+3)*132 + row] = v.w;
        }
        __syncthreads();
        #pragma unroll
        for (int kq=0;kq<4;kq++){
            float4 av[8];
            #pragma unroll
            for (int i=0;i<8;i++) av[i] = *(const float4*)(As + (ty*8+i)*20 + kq*4);
            #pragma unroll
            for (int kk=0;kk<4;kk++){
                ull a2[8];
                #pragma unroll
                for (int i=0;i<8;i++){
                    float a = (kk==0)?av[i].x:(kk==1)?av[i].y:(kk==2)?av[i].z:av[i].w;
                    a2[i] = dup2(a);
                }
                const int k = kq*4+kk;
                #pragma unroll
                for (int q=0;q<2;q++){
                    ulonglong2 bv = *(const ulonglong2*)(Bs + k*132 + tx*4 + q*64);
                    #pragma unroll
                    for (int i=0;i<8;i++){ ffma2(acc[i][q][0], a2[i], bv.x);
                                           ffma2(acc[i][q][1], a2[i], bv.y); }
                }
            }
        }
        __syncthreads();
    }
    #pragma unroll
    for (int i=0;i<8;i++){
        int gm = m0 + ty*8 + i;
        #pragma unroll
        for (int q=0;q<2;q++){
            int gn = n0 + tx*4 + q*64;
            float2 p0 = unpk(acc[i][q][0]);
            float2 p1 = unpk(acc[i][q][1]);
            float4 bb = *(const float4*)(cat_b + gn);
            *(float4*)(g_enc_out + (size_t)gm*512 + gn) =
                make_float4(p0.x+bb.x, p0.y+bb.y, p1.x+bb.z, p1.y+bb.w);
        }
    }
}

__global__ void avg_kernel()
{
    int b = blockIdx.x, e = threadIdx.x;
    float s = 0.f;
    #pragma unroll 5
    for (int si=0; si<SS; si++) s += g_enc_out[(b*SS+si)*EE + e];
    g_avg[b*EE + e] = s * (1.0f/50.0f);
}

__global__ void h0_kernel(const float* __restrict__ scale_W, const float* __restrict__ scale_b)
{
    int gid = blockIdx.x*blockDim.x + threadIdx.x;
    int b = gid >> 10, h = gid & 1023;
    const float4* a = (const float4*)(g_avg + b*EE);
    const float4* w = (const float4*)(scale_W + (size_t)h*EE);
    float s = 0.f;
    #pragma unroll 8
    for (int i=0;i<128;i++){
        float4 av=a[i], wv=w[i];
        s += av.x*wv.x + av.y*wv.y + av.z*wv.z + av.w*wv.w;
    }
    float v = fmaxf(s + scale_b[h], 0.f);
    g_h[gid] = v; g_c[gid] = v;
}

__global__ void attn_kernel(const float* __restrict__ attn_W, const int* __restrict__ src)
{
    int b = blockIdx.x, tid = threadIdx.x;
    __shared__ float sc[56];
    __shared__ float aw[56];
    int w = tid >> 5, lane = tid & 31;
    for (int s = w; s < SS; s += 8){
        const float* row = g_enc_out + (size_t)(b*SS+s)*EE;
        float a = 0.f;
        for (int e = lane; e < EE; e += 32) a += row[e]*attn_W[e];
        #pragma unroll
        for (int o=16;o>0;o>>=1) a += __shfl_xor_sync(0xffffffffu, a, o);
        if (lane==0) sc[s] = a;
    }
    __syncthreads();
    if (tid == 0){
        float mx = -1e30f;
        for (int s=0;s<SS;s++) mx = fmaxf(mx, sc[s]);
        float tot = 0.f;
        for (int s=0;s<SS;s++){
            float e = (src[b*SS+s]==0) ? 0.f : expf(sc[s]-mx);
            aw[s] = e; tot += e;
        }
        float inv = 1.f/tot;
        for (int s=0;s<SS;s++) aw[s] *= inv;
    }
    __syncthreads();
    for (int e = tid; e < EE; e += blockDim.x){
        float a = 0.f;
        #pragma unroll 5
        for (int s=0;s<SS;s++) a += aw[s]*g_enc_out[(size_t)(b*SS+s)*EE + e];
        g_ctx[b*EE + e] = a;
    }
}

__global__ void gconst_kernel(const float* __restrict__ W_ih,
                              const float* __restrict__ b_ih, const float* __restrict__ b_hh)
{
    int gid = blockIdx.x*blockDim.x + threadIdx.x;
    int b = gid >> 12, j = gid & 4095;
    const float4* c4 = (const float4*)(g_ctx + b*EE);
    const float4* w4 = (const float4*)(W_ih + (size_t)j*1024 + 512);
    float s = 0.f;
    #pragma unroll 8
    for (int i=0;i<128;i++){
        float4 cv=c4[i], wv=w4[i];
        s += cv.x*wv.x + cv.y*wv.y + cv.z*wv.z + cv.w*wv.w;
    }
    g_gconst[gid] = s + b_ih[j] + b_hh[j];
}

// ============================================================
// Hoisted token-embedding GEMM for ALL steps:
// pre[r=t*64+b, j] = dec_emb[tok[b,t]] . W_ih[j,0:512] + gconst[b,j]
// M=3200, N=4096, K=512 (fp32 FFMA2)
// ============================================================
__global__ __launch_bounds__(256)
void dec_pre(const int* __restrict__ tgt, const float* __restrict__ dec_emb,
             const float* __restrict__ W_ih)
{
    __shared__ __align__(16) float As[128*20];
    __shared__ __align__(16) float Bs[16*132];
    const int m0 = blockIdx.x * 128;
    const int n0 = blockIdx.y * 128;
    const int tid = threadIdx.x;
    const int tx = tid & 15, ty = tid >> 4;

    ull acc[8][2][2];
    #pragma unroll
    for (int i=0;i<8;i++)
        #pragma unroll
        for (int q=0;q<2;q++){ acc[i][q][0]=0ull; acc[i][q][1]=0ull; }

    for (int kt = 0; kt < 512; kt += 16){
        #pragma unroll
        for (int l=0;l<2;l++){
            int f4 = tid + 256*l;
            int row = f4 >> 2, k4 = (f4 & 3) << 2;
            int r = m0 + row;
            int tok = tgt[(r & 63)*50 + (r >> 6)];
            float4 v = *(const float4*)(dec_emb + (size_t)tok*512 + kt + k4);
            *(float4*)(As + row*20 + k4) = v;
        }
        #pragma unroll
        for (int l=0;l<2;l++){
            int f4 = tid + 256*l;
            int row = f4 >> 2, k4 = (f4 & 3) << 2;
            float4 v = *(const float4*)(W_ih + (size_t)(n0+row)*1024 + kt + k4);
            Bs[(k4+0)*132 + row] = v.x;
            Bs[(k4+1)*132 + row] = v.y;
            Bs[(k4+2)*132 + row] = v.z;
            Bs[(k4+3)*132 + row] = v.w;
        }
        __syncthreads();
        #pragma unroll
        for (int kq=0;kq<4;kq++){
            float4 av[8];
            #pragma unroll
            for (int i=0;i<8;i++) av[i] = *(const float4*)(As + (ty*8+i)*20 + kq*4);
            #pragma unroll
            for (int kk=0;kk<4;kk++){
                ull a2[8];
                #pragma unroll
                for (int i=0;i<8;i++){
                    float a = (kk==0)?av[i].x:(kk==1)?av[i].y:(kk==2)?av[i].z:av[i].w;
                    a2[i] = dup2(a);
                }
                const int k = kq*4+kk;
                #pragma unroll
                for (int q=0;q<2;q++){
                    ulonglong2 bv = *(const ulonglong2*)(Bs + k*132 + tx*4 + q*64);
                    #pragma unroll
                    for (int i=0;i<8;i++){ ffma2(acc[i][q][0], a2[i], bv.x);
                                           ffma2(acc[i][q][1], a2[i], bv.y); }
                }
            }
        }
        __syncthreads();
    }
    #pragma unroll
    for (int i=0;i<8;i++){
        int gm = m0 + ty*8 + i;
        int b = gm & 63;
        #pragma unroll
        for (int q=0;q<2;q++){
            int gn = n0 + tx*4 + q*64;
            float2 p0 = unpk(acc[i][q][0]);
            float2 p1 = unpk(acc[i][q][1]);
            float4 gc = *(const float4*)(g_gconst + (size_t)b*G4H + gn);
            *(float4*)(g_pre + (size_t)gm*G4H + gn) =
                make_float4(p0.x+gc.x, p0.y+gc.y, p1.x+gc.z, p1.y+gc.w);
        }
    }
}

// ============================================================
// Per-step gates GEMM (split-K over K=1024): part = h . W_hh^T
// ============================================================
__global__ __launch_bounds__(128)
void gates_gemm(const float* __restrict__ W_hh)
{
    __shared__ __align__(16) float As[64*20];
    __shared__ __align__(16) float Bs[16*132];
    const int n0 = blockIdx.x * 128;
    const int kbase = blockIdx.y * KCHUNK;
    const int tid = threadIdx.x;
    const int tx = tid & 15, ty = tid >> 4;

    ull acc[8][2][2];
    #pragma unroll
    for (int i=0;i<8;i++)
        #pragma unroll
        for (int q=0;q<2;q++){ acc[i][q][0]=0ull; acc[i][q][1]=0ull; }

    for (int kt = 0; kt < KCHUNK; kt += 16){
        const int kg0 = kbase + kt;
        #pragma unroll
        for (int l=0;l<2;l++){
            int f4 = tid + 128*l;
            int row = f4 >> 2, k4 = (f4 & 3) << 2;
            float4 v = *(const float4*)(g_h + row*1024 + kg0 + k4);
            *(float4*)(As + row*20 + k4) = v;
        }
        #pragma unroll
        for (int l=0;l<4;l++){
            int f4 = tid + 128*l;
            int row = f4 >> 2, k4 = (f4 & 3) << 2;
            float4 v = *(const float4*)(W_hh + (size_t)(n0+row)*1024 + kg0 + k4);
            Bs[(k4+0)*132 + row] = v.x;
            Bs[(k4+1)*132 + row] = v.y;
            Bs[(k4+2)*132 + row] = v.z;
            Bs[(k4+3)*132 + row] = v.w;
        }
        __syncthreads();
        #pragma unroll
        for (int kq=0;kq<4;kq++){
            float4 av[8];
            #pragma unroll
            for (int i=0;i<8;i++) av[i] = *(const float4*)(As + (ty*8+i)*20 + kq*4);
            #pragma unroll
            for (int kk=0;kk<4;kk++){
                ull a2[8];
                #pragma unroll
                for (int i=0;i<8;i++){
                    float a = (kk==0)?av[i].x:(kk==1)?av[i].y:(kk==2)?av[i].z:av[i].w;
                    a2[i] = dup2(a);
                }
                const int k = kq*4+kk;
                #pragma unroll
                for (int q=0;q<2;q++){
                    ulonglong2 bv = *(const ulonglong2*)(Bs + k*132 + tx*4 + q*64);
                    #pragma unroll
                    for (int i=0;i<8;i++){ ffma2(acc[i][q][0], a2[i], bv.x);
                                           ffma2(acc[i][q][1], a2[i], bv.y); }
                }
            }
        }
        __syncthreads();
    }
    float* outp = g_part + (size_t)blockIdx.y*(BB*G4H);
    #pragma unroll
    for (int i=0;i<8;i++){
        int m = ty*8 + i;
        #pragma unroll
        for (int q=0;q<2;q++){
            int n = n0 + tx*4 + q*64;
            float2 p0 = unpk(acc[i][q][0]);
            float2 p1 = unpk(acc[i][q][1]);
            *(float4*)(outp + (size_t)m*G4H + n) = make_float4(p0.x, p0.y, p1.x, p1.y);
        }
    }
}

// ============================================================
// LSTM pointwise; emits h rows into A' = [Ah | Ah | Al]
// ============================================================
__global__ void lstm_pw(int t)
{
    int gid = blockIdx.x*blockDim.x + threadIdx.x;
    int b = gid >> 10, h = gid & 1023;
    size_t prow = (size_t)(t*64 + b)*G4H;
    float gi = g_pre[prow + h];
    float gf = g_pre[prow + 1024 + h];
    float gg = g_pre[prow + 2048 + h];
    float go = g_pre[prow + 3072 + h];
    int base = b*G4H;
    #pragma unroll
    for (int s=0;s<KSPLIT;s++){
        const float* p = g_part + (size_t)s*(BB*G4H) + base;
        gi += p[h]; gf += p[1024+h]; gg += p[2048+h]; go += p[3072+h];
    }
    float c  = g_c[gid];
    float ii = 1.f/(1.f+expf(-gi));
    float ff = 1.f/(1.f+expf(-gf));
    float oo = 1.f/(1.f+expf(-go));
    float gt = tanhf(gg);
    float cn = ff*c + ii*gt;
    float hn = oo*tanhf(cn);
    g_c[gid] = cn; g_h[gid] = hn;

    __nv_bfloat16 hhi = __float2bfloat16_rn(hn);
    float hif = __bfloat162float(hhi);
    __nv_bfloat16 hlo = __float2bfloat16_rn(hn - hif);
    size_t arow = (size_t)(t*64 + b)*KCAT;
    g_Acat[arow + h]        = hhi;
    g_Acat[arow + 1024 + h] = hhi;
    g_Acat[arow + 2048 + h] = hlo;
}

// ============================================================
// proj_W fp32 -> B' = [Bh | Bl | Bh] (bf16)
// ============================================================
__global__ __launch_bounds__(256)
void conv_w(const float* __restrict__ W)
{
    size_t i = (size_t)blockIdx.x*blockDim.x + threadIdx.x;   // 8,192,000 float4s
    int n = (int)(i >> 8);
    int k = (int)(i & 255) * 4;
    float4 v = ((const float4*)W)[i];
    __nv_bfloat16 h0 = __float2bfloat16_rn(v.x);
    __nv_bfloat16 h1 = __float2bfloat16_rn(v.y);
    __nv_bfloat16 h2 = __float2bfloat16_rn(v.z);
    __nv_bfloat16 h3 = __float2bfloat16_rn(v.w);
    __nv_bfloat16 l0 = __float2bfloat16_rn(v.x - __bfloat162float(h0));
    __nv_bfloat16 l1 = __float2bfloat16_rn(v.y - __bfloat162float(h1));
    __nv_bfloat16 l2 = __float2bfloat16_rn(v.z - __bfloat162float(h2));
    __nv_bfloat16 l3 = __float2bfloat16_rn(v.w - __bfloat162float(h3));
    ull hi, lo;
    asm("mov.b64 %0, {%1,%2,%3,%4};" : "=l"(hi)
        : "h"(*(unsigned short*)&h0), "h"(*(unsigned short*)&h1),
          "h"(*(unsigned short*)&h2), "h"(*(unsigned short*)&h3));
    asm("mov.b64 %0, {%1,%2,%3,%4};" : "=l"(lo)
        : "h"(*(unsigned short*)&l0), "h"(*(unsigned short*)&l1),
          "h"(*(unsigned short*)&l2), "h"(*(unsigned short*)&l3));
    size_t rb = (size_t)n*KCAT;
    *(ull*)(g_Bcat + rb + k)        = hi;
    *(ull*)(g_Bcat + rb + 1024 + k) = lo;
    *(ull*)(g_Bcat + rb + 2048 + k) = hi;
}

// ============================================================
// Projection via mma.sync bf16: out = A'(3200xK) . B'(32000xK)^T + bias
// CTA 128x128, 8 warps (4M x 2N), 3-stage cp.async pipeline, K=3072.
// smem rows padded to 80B -> conflict-free ldmatrix.
// ============================================================
#define NSTG 3
#define TSTAGE 10240            /* 128 rows * 80 B */
#define SM_PROJ (NSTG*2*TSTAGE) /* 61440 */

__global__ __launch_bounds__(256)
void proj_mma(float* __restrict__ out, const float* __restrict__ bias)
{
    extern __shared__ __align__(16) char sm[];
    const uint32_t uA = smem_u32(sm);
    const uint32_t uB = uA + NSTG*TSTAGE;
    const int tid = threadIdx.x;
    const int wid = tid >> 5, lane = tid & 31;
    const int m0 = blockIdx.x * 128;
    const int n0 = blockIdx.y * 128;
    const int wm = wid & 3, wn = wid >> 2;

    const int lrow = tid >> 2;            // 0..63
    const int lc   = (tid & 3);           // 16B chunk in 64B row

    float acc[2][8][4];
    #pragma unroll
    for (int a=0;a<2;a++)
        #pragma unroll
        for (int j=0;j<8;j++)
            #pragma unroll
            for (int x=0;x<4;x++) acc[a][j][x] = 0.f;

    const __nv_bfloat16* gA = g_Acat + (size_t)m0*KCAT;
    const __nv_bfloat16* gB = g_Bcat + (size_t)n0*KCAT;

    // ---- stage loader ----
    auto load_stage = [&](int slot, int ks){
        int k0 = ks * 32;
        #pragma unroll
        for (int half = 0; half < 2; half++){
            int row = lrow + half*64;
            cpasync16(uA + slot*TSTAGE + row*80 + lc*16,
                      gA + (size_t)row*KCAT + k0 + lc*8);
            cpasync16(uB + slot*TSTAGE + row*80 + lc*16,
                      gB + (size_t)row*KCAT + k0 + lc*8);
        }
        cp_commit();
    };

    load_stage(0, 0);
    load_stage(1, 1);

    const int g  = lane >> 3;     // ldmatrix tile group 0..3
    const int lr = lane & 7;

    for (int ks = 0; ks < 96; ks++){
        asm volatile("cp.async.wait_group 1;");
        __syncthreads();
        int ld = ks + NSTG - 1;
        if (ld < 96) load_stage(ld % NSTG, ld);
        else cp_commit();

        const uint32_t bufA = uA + (ks % NSTG)*TSTAGE;
        const uint32_t bufB = uB + (ks % NSTG)*TSTAGE;

        #pragma unroll
        for (int kk = 0; kk < 32; kk += 16){
            uint32_t afr[2][4];
            #pragma unroll
            for (int mi = 0; mi < 2; mi++){
                int row = wm*32 + mi*16 + ((g & 1) ? 8 : 0) + lr;
                int kof = kk + (g >> 1)*8;
                ldm4(afr[mi], bufA + row*80 + kof*2);
            }
            uint32_t bfr[4][4];
            #pragma unroll
            for (int p = 0; p < 4; p++){
                int row = wn*64 + p*16 + (g >> 1)*8 + lr;
                int kof = kk + (g & 1)*8;
                ldm4(bfr[p], bufB + row*80 + kof*2);
            }
            #pragma unroll
            for (int mi = 0; mi < 2; mi++)
                #pragma unroll
                for (int j = 0; j < 8; j++){
                    int p = j >> 1, h2 = (j & 1)*2;
                    mma16816(acc[mi][j], afr[mi], bfr[p][h2], bfr[p][h2+1]);
                }
        }
        __syncthreads();
    }

    // ---- epilogue ----
    const int tm = lane >> 2;
    const int tn = (lane & 3)*2;
    #pragma unroll
    for (int mi = 0; mi < 2; mi++){
        #pragma unroll
        for (int j = 0; j < 8; j++){
            int gn = n0 + wn*64 + j*8 + tn;
            float2 bb = *(const float2*)(bias + gn);
            int gm0 = m0 + wm*32 + mi*16 + tm;
            if (gm0 < MPROJ){
                float2 o; o.x = acc[mi][j][0] + bb.x; o.y = acc[mi][j][1] + bb.y;
                *(float2*)(out + (size_t)gm0*VTS + gn) = o;
            }
            int gm1 = gm0 + 8;
            if (gm1 < MPROJ){
                float2 o; o.x = acc[mi][j][2] + bb.x; o.y = acc[mi][j][3] + bb.y;
                *(float2*)(out + (size_t)gm1*VTS + gn) = o;
            }
        }
    }
}

// ============================================================
extern "C" void kernel_launch(void* const* d_in, const int* in_sizes, int n_in,
                              void* d_out, int out_size)
{
    const int*   src      = (const int*)  d_in[0];
    const int*   pos      = (const int*)  d_in[2];
    const int*   tgt      = (const int*)  d_in[3];
    const float* enc_emb  = (const float*)d_in[4];
    const float* pos_emb  = (const float*)d_in[5];
    const float* cat_W    = (const float*)d_in[6];
    const float* cat_b    = (const float*)d_in[7];
    const float* scale_W  = (const float*)d_in[8];
    const float* scale_b  = (const float*)d_in[9];
    const float* dec_emb  = (const float*)d_in[10];
    const float* attn_W   = (const float*)d_in[11];
    const float* W_ih     = (const float*)d_in[13];
    const float* W_hh     = (const float*)d_in[14];
    const float* b_ih     = (const float*)d_in[15];
    const float* b_hh     = (const float*)d_in[16];
    const float* proj_W   = (const float*)d_in[17];
    const float* proj_b   = (const float*)d_in[18];
    float* out = (float*)d_out;

    cudaFuncSetAttribute(proj_mma, cudaFuncAttributeMaxDynamicSharedMemorySize, SM_PROJ);

    // B' conversion (independent; overlaps encoder work in-order on stream)
    conv_w<<<32000, 256>>>(proj_W);

    // Encoder
    enc_gemm<<<dim3(25,4), 256>>>(src, pos, enc_emb, pos_emb, cat_W, cat_b);
    avg_kernel<<<64, 512>>>();
    h0_kernel<<<256, 256>>>(scale_W, scale_b);

    // Loop-invariant attention context + hoisted per-step constants
    attn_kernel<<<64, 256>>>(attn_W, src);
    gconst_kernel<<<1024, 256>>>(W_ih, b_ih, b_hh);
    dec_pre<<<dim3(25,32), 256>>>(tgt, dec_emb, W_ih);

    // Recurrence: only h . W_hh^T is sequential now (K=1024)
    for (int t = 0; t < NSTEP; t++){
        gates_gemm<<<dim3(32, KSPLIT), 128>>>(W_hh);
        lstm_pw<<<256, 256>>>(t);
    }

    // Tensor-core projection (single GEMM, K=3072 3-term concat)
    proj_mma<<<dim3(25,250), 256, SM_PROJ>>>(out, proj_b);
}

// round 4
// speedup vs baseline: 1.5135x; 1.0256x over previous
#include <cuda_runtime.h>
#include <cuda_bf16.h>
#include <math.h>
#include <stdint.h>

// Problem dims
#define BB 64
#define SS 50
#define EE 512
#define HH 1024
#define VTS 32000
#define NSTEP 49
#define MPROJ (NSTEP*BB)   /* 3136 */
#define MPAD  3200
#define G4H 4096
#define KSPLIT 8
#define KCHUNK 128         /* 1024/8 */
#define KCAT 3072          /* 3-term concat K */

typedef unsigned long long ull;

// ---------- packed f32x2 helpers ----------
__device__ __forceinline__ ull dup2(float x){
    ull r; asm("mov.b64 %0, {%1, %1};" : "=l"(r) : "f"(x)); return r;
}
__device__ __forceinline__ void ffma2(ull &d, ull a, ull b){
    asm("fma.rn.f32x2 %0, %1, %2, %0;" : "+l"(d) : "l"(a), "l"(b));
}
__device__ __forceinline__ float2 unpk(ull v){
    float2 f; asm("mov.b64 {%0, %1}, %2;" : "=f"(f.x), "=f"(f.y) : "l"(v)); return f;
}

// ---------- baseline-PTX tensor helpers (no 'a'-target features) ----------
__device__ __forceinline__ uint32_t smem_u32(const void* p){
    uint32_t a;
    asm("{ .reg .u64 t; cvta.to.shared.u64 t, %1; cvt.u32.u64 %0, t; }" : "=r"(a) : "l"(p));
    return a;
}
__device__ __forceinline__ void cpasync16(uint32_t dst, const void* src){
    asm volatile("cp.async.cg.shared.global [%0], [%1], 16;" :: "r"(dst), "l"(src));
}
__device__ __forceinline__ void cp_commit(){
    asm volatile("cp.async.commit_group;");
}
__device__ __forceinline__ void ldm4(uint32_t* r, uint32_t a){
    asm volatile("ldmatrix.sync.aligned.m8n8.x4.shared.b16 {%0,%1,%2,%3}, [%4];"
        : "=r"(r[0]), "=r"(r[1]), "=r"(r[2]), "=r"(r[3]) : "r"(a));
}
__device__ __forceinline__ void mma16816(float* c, const uint32_t* a, uint32_t b0, uint32_t b1){
    asm volatile("mma.sync.aligned.m16n8k16.row.col.f32.bf16.bf16.f32 "
        "{%0,%1,%2,%3}, {%4,%5,%6,%7}, {%8,%9}, {%0,%1,%2,%3};"
        : "+f"(c[0]), "+f"(c[1]), "+f"(c[2]), "+f"(c[3])
        : "r"(a[0]), "r"(a[1]), "r"(a[2]), "r"(a[3]), "r"(b0), "r"(b1));
}

// ---------- scratch ----------
__device__ float g_enc_out[BB*SS*EE];
__device__ float g_avg[BB*EE];
__device__ float g_ctx[BB*EE];
__device__ float g_h[BB*HH];
__device__ float g_c[BB*HH];
__device__ float g_gconst[BB*G4H];
__device__ float g_part[KSPLIT*BB*G4H];
__device__ float g_pre[MPAD*G4H];                    // per-step const gate input
__device__ __nv_bfloat16 g_Acat[(size_t)MPAD*KCAT];  // [Ah|Ah|Al] rows (zero beyond 3136)
__device__ __nv_bfloat16 g_Bcat[(size_t)VTS*KCAT];   // [Bh|Bl|Bh] rows

// ============================================================
// Encoder GEMM (fp32 FFMA2) — unchanged from round 1
// ============================================================
__global__ __launch_bounds__(256)
void enc_gemm(const int* __restrict__ src, const int* __restrict__ pos,
              const float* __restrict__ enc_emb, const float* __restrict__ pos_emb,
              const float* __restrict__ cat_W, const float* __restrict__ cat_b)
{
    __shared__ __align__(16) float As[128*20];
    __shared__ __align__(16) float Bs[16*132];
    const int m0 = blockIdx.x * 128;
    const int n0 = blockIdx.y * 128;
    const int tid = threadIdx.x;
    const int tx = tid & 15, ty = tid >> 4;

    ull acc[8][2][2];
    #pragma unroll
    for (int i=0;i<8;i++)
        #pragma unroll
        for (int q=0;q<2;q++){ acc[i][q][0]=0ull; acc[i][q][1]=0ull; }

    for (int kt = 0; kt < 1024; kt += 16){
        #pragma unroll
        for (int l=0;l<2;l++){
            int f4 = tid + 256*l;
            int row = f4 >> 2, k4 = (f4 & 3) << 2;
            int kg = kt + k4;
            int r = m0 + row;
            float4 v;
            if (kg < 512) v = *(const float4*)(enc_emb + (size_t)src[r]*512 + kg);
            else          v = *(const float4*)(pos_emb + (size_t)pos[r]*512 + (kg - 512));
            *(float4*)(As + row*20 + k4) = v;
        }
        #pragma unroll
        for (int l=0;l<2;l++){
            int f4 = tid + 256*l;
            int row = f4 >> 2, k4 = (f4 & 3) << 2;
            float4 v = *(const float4*)(cat_W + (size_t)(n0+row)*1024 + kt + k4);
            Bs[(k4+0)*132 + row] = v.x;
            Bs[(k4+1)*132 + row] = v.y;
            Bs[(k4+2)*132 + row] = v.z;
            Bs[(k4+3)*132 + row] = v.w;
        }
        __syncthreads();
        #pragma unroll
        for (int kq=0;kq<4;kq++){
            float4 av[8];
            #pragma unroll
            for (int i=0;i<8;i++) av[i] = *(const float4*)(As + (ty*8+i)*20 + kq*4);
            #pragma unroll
            for (int kk=0;kk<4;kk++){
                ull a2[8];
                #pragma unroll
                for (int i=0;i<8;i++){
                    float a = (kk==0)?av[i].x:(kk==1)?av[i].y:(kk==2)?av[i].z:av[i].w;
                    a2[i] = dup2(a);
                }
                const int k = kq*4+kk;
                #pragma unroll
                for (int q=0;q<2;q++){
                    ulonglong2 bv = *(const ulonglong2*)(Bs + k*132 + tx*4 + q*64);
                    #pragma unroll
                    for (int i=0;i<8;i++){ ffma2(acc[i][q][0], a2[i], bv.x);
                                           ffma2(acc[i][q][1], a2[i], bv.y); }
                }
            }
        }
        __syncthreads();
    }
    #pragma unroll
    for (int i=0;i<8;i++){
        int gm = m0 + ty*8 + i;
        #pragma unroll
        for (int q=0;q<2;q++){
            int gn = n0 + tx*4 + q*64;
            float2 p0 = unpk(acc[i][q][0]);
            float2 p1 = unpk(acc[i][q][1]);
            float4 bb = *(const float4*)(cat_b + gn);
            *(float4*)(g_enc_out + (size_t)gm*512 + gn) =
                make_float4(p0.x+bb.x, p0.y+bb.y, p1.x+bb.z, p1.y+bb.w);
        }
    }
}

__global__ void avg_kernel()
{
    int b = blockIdx.x, e = threadIdx.x;
    float s = 0.f;
    #pragma unroll 5
    for (int si=0; si<SS; si++) s += g_enc_out[(b*SS+si)*EE + e];
    g_avg[b*EE + e] = s * (1.0f/50.0f);
}

__global__ void h0_kernel(const float* __restrict__ scale_W, const float* __restrict__ scale_b)
{
    int gid = blockIdx.x*blockDim.x + threadIdx.x;
    int b = gid >> 10, h = gid & 1023;
    const float4* a = (const float4*)(g_avg + b*EE);
    const float4* w = (const float4*)(scale_W + (size_t)h*EE);
    float s = 0.f;
    #pragma unroll 8
    for (int i=0;i<128;i++){
        float4 av=a[i], wv=w[i];
        s += av.x*wv.x + av.y*wv.y + av.z*wv.z + av.w*wv.w;
    }
    float v = fmaxf(s + scale_b[h], 0.f);
    g_h[gid] = v; g_c[gid] = v;
}

__global__ void attn_kernel(const float* __restrict__ attn_W, const int* __restrict__ src)
{
    int b = blockIdx.x, tid = threadIdx.x;
    __shared__ float sc[56];
    __shared__ float aw[56];
    int w = tid >> 5, lane = tid & 31;
    for (int s = w; s < SS; s += 8){
        const float* row = g_enc_out + (size_t)(b*SS+s)*EE;
        float a = 0.f;
        for (int e = lane; e < EE; e += 32) a += row[e]*attn_W[e];
        #pragma unroll
        for (int o=16;o>0;o>>=1) a += __shfl_xor_sync(0xffffffffu, a, o);
        if (lane==0) sc[s] = a;
    }
    __syncthreads();
    if (tid == 0){
        float mx = -1e30f;
        for (int s=0;s<SS;s++) mx = fmaxf(mx, sc[s]);
        float tot = 0.f;
        for (int s=0;s<SS;s++){
            float e = (src[b*SS+s]==0) ? 0.f : expf(sc[s]-mx);
            aw[s] = e; tot += e;
        }
        float inv = 1.f/tot;
        for (int s=0;s<SS;s++) aw[s] *= inv;
    }
    __syncthreads();
    for (int e = tid; e < EE; e += blockDim.x){
        float a = 0.f;
        #pragma unroll 5
        for (int s=0;s<SS;s++) a += aw[s]*g_enc_out[(size_t)(b*SS+s)*EE + e];
        g_ctx[b*EE + e] = a;
    }
}

__global__ void gconst_kernel(const float* __restrict__ W_ih,
                              const float* __restrict__ b_ih, const float* __restrict__ b_hh)
{
    int gid = blockIdx.x*blockDim.x + threadIdx.x;
    int b = gid >> 12, j = gid & 4095;
    const float4* c4 = (const float4*)(g_ctx + b*EE);
    const float4* w4 = (const float4*)(W_ih + (size_t)j*1024 + 512);
    float s = 0.f;
    #pragma unroll 8
    for (int i=0;i<128;i++){
        float4 cv=c4[i], wv=w4[i];
        s += cv.x*wv.x + cv.y*wv.y + cv.z*wv.z + cv.w*wv.w;
    }
    g_gconst[gid] = s + b_ih[j] + b_hh[j];
}

// ============================================================
// Hoisted token-embedding GEMM for ALL steps:
// pre[r=t*64+b, j] = dec_emb[tok[b,t]] . W_ih[j,0:512] + gconst[b,j]
// M=3200, N=4096, K=512 (fp32 FFMA2)
// ============================================================
__global__ __launch_bounds__(256)
void dec_pre(const int* __restrict__ tgt, const float* __restrict__ dec_emb,
             const float* __restrict__ W_ih)
{
    __shared__ __align__(16) float As[128*20];
    __shared__ __align__(16) float Bs[16*132];
    const int m0 = blockIdx.x * 128;
    const int n0 = blockIdx.y * 128;
    const int tid = threadIdx.x;
    const int tx = tid & 15, ty = tid >> 4;

    ull acc[8][2][2];
    #pragma unroll
    for (int i=0;i<8;i++)
        #pragma unroll
        for (int q=0;q<2;q++){ acc[i][q][0]=0ull; acc[i][q][1]=0ull; }

    for (int kt = 0; kt < 512; kt += 16){
        #pragma unroll
        for (int l=0;l<2;l++){
            int f4 = tid + 256*l;
            int row = f4 >> 2, k4 = (f4 & 3) << 2;
            int r = m0 + row;
            int tok = tgt[(r & 63)*50 + (r >> 6)];
            float4 v = *(const float4*)(dec_emb + (size_t)tok*512 + kt + k4);
            *(float4*)(As + row*20 + k4) = v;
        }
        #pragma unroll
        for (int l=0;l<2;l++){
            int f4 = tid + 256*l;
            int row = f4 >> 2, k4 = (f4 & 3) << 2;
            float4 v = *(const float4*)(W_ih + (size_t)(n0+row)*1024 + kt + k4);
            Bs[(k4+0)*132 + row] = v.x;
            Bs[(k4+1)*132 + row] = v.y;
            Bs[(k4+2)*132 + row] = v.z;
            Bs[(k4+3)*132 + row] = v.w;
        }
        __syncthreads();
        #pragma unroll
        for (int kq=0;kq<4;kq++){
            float4 av[8];
            #pragma unroll
            for (int i=0;i<8;i++) av[i] = *(const float4*)(As + (ty*8+i)*20 + kq*4);
            #pragma unroll
            for (int kk=0;kk<4;kk++){
                ull a2[8];
                #pragma unroll
                for (int i=0;i<8;i++){
                    float a = (kk==0)?av[i].x:(kk==1)?av[i].y:(kk==2)?av[i].z:av[i].w;
                    a2[i] = dup2(a);
                }
                const int k = kq*4+kk;
                #pragma unroll
                for (int q=0;q<2;q++){
                    ulonglong2 bv = *(const ulonglong2*)(Bs + k*132 + tx*4 + q*64);
                    #pragma unroll
                    for (int i=0;i<8;i++){ ffma2(acc[i][q][0], a2[i], bv.x);
                                           ffma2(acc[i][q][1], a2[i], bv.y); }
                }
            }
        }
        __syncthreads();
    }
    #pragma unroll
    for (int i=0;i<8;i++){
        int gm = m0 + ty*8 + i;
        int b = gm & 63;
        #pragma unroll
        for (int q=0;q<2;q++){
            int gn = n0 + tx*4 + q*64;
            float2 p0 = unpk(acc[i][q][0]);
            float2 p1 = unpk(acc[i][q][1]);
            float4 gc = *(const float4*)(g_gconst + (size_t)b*G4H + gn);
            *(float4*)(g_pre + (size_t)gm*G4H + gn) =
                make_float4(p0.x+gc.x, p0.y+gc.y, p1.x+gc.z, p1.y+gc.w);
        }
    }
}

// ============================================================
// Per-step gates GEMM (split-K over K=1024): part = h . W_hh^T
// ============================================================
__global__ __launch_bounds__(128)
void gates_gemm(const float* __restrict__ W_hh)
{
    __shared__ __align__(16) float As[64*20];
    __shared__ __align__(16) float Bs[16*132];
    const int n0 = blockIdx.x * 128;
    const int kbase = blockIdx.y * KCHUNK;
    const int tid = threadIdx.x;
    const int tx = tid & 15, ty = tid >> 4;

    ull acc[8][2][2];
    #pragma unroll
    for (int i=0;i<8;i++)
        #pragma unroll
        for (int q=0;q<2;q++){ acc[i][q][0]=0ull; acc[i][q][1]=0ull; }

    for (int kt = 0; kt < KCHUNK; kt += 16){
        const int kg0 = kbase + kt;
        #pragma unroll
        for (int l=0;l<2;l++){
            int f4 = tid + 128*l;
            int row = f4 >> 2, k4 = (f4 & 3) << 2;
            float4 v = *(const float4*)(g_h + row*1024 + kg0 + k4);
            *(float4*)(As + row*20 + k4) = v;
        }
        #pragma unroll
        for (int l=0;l<4;l++){
            int f4 = tid + 128*l;
            int row = f4 >> 2, k4 = (f4 & 3) << 2;
            float4 v = *(const float4*)(W_hh + (size_t)(n0+row)*1024 + kg0 + k4);
            Bs[(k4+0)*132 + row] = v.x;
            Bs[(k4+1)*132 + row] = v.y;
            Bs[(k4+2)*132 + row] = v.z;
            Bs[(k4+3)*132 + row] = v.w;
        }
        __syncthreads();
        #pragma unroll
        for (int kq=0;kq<4;kq++){
            float4 av[8];
            #pragma unroll
            for (int i=0;i<8;i++) av[i] = *(const float4*)(As + (ty*8+i)*20 + kq*4);
            #pragma unroll
            for (int kk=0;kk<4;kk++){
                ull a2[8];
                #pragma unroll
                for (int i=0;i<8;i++){
                    float a = (kk==0)?av[i].x:(kk==1)?av[i].y:(kk==2)?av[i].z:av[i].w;
                    a2[i] = dup2(a);
                }
                const int k = kq*4+kk;
                #pragma unroll
                for (int q=0;q<2;q++){
                    ulonglong2 bv = *(const ulonglong2*)(Bs + k*132 + tx*4 + q*64);
                    #pragma unroll
                    for (int i=0;i<8;i++){ ffma2(acc[i][q][0], a2[i], bv.x);
                                           ffma2(acc[i][q][1], a2[i], bv.y); }
                }
            }
        }
        __syncthreads();
    }
    float* outp = g_part + (size_t)blockIdx.y*(BB*G4H);
    #pragma unroll
    for (int i=0;i<8;i++){
        int m = ty*8 + i;
        #pragma unroll
        for (int q=0;q<2;q++){
            int n = n0 + tx*4 + q*64;
            float2 p0 = unpk(acc[i][q][0]);
            float2 p1 = unpk(acc[i][q][1]);
            *(float4*)(outp + (size_t)m*G4H + n) = make_float4(p0.x, p0.y, p1.x, p1.y);
        }
    }
}

// ============================================================
// LSTM pointwise; emits h rows into A' = [Ah | Ah | Al]
// ============================================================
__global__ void lstm_pw(int t)
{
    int gid = blockIdx.x*blockDim.x + threadIdx.x;
    int b = gid >> 10, h = gid & 1023;
    size_t prow = (size_t)(t*64 + b)*G4H;
    float gi = g_pre[prow + h];
    float gf = g_pre[prow + 1024 + h];
    float gg = g_pre[prow + 2048 + h];
    float go = g_pre[prow + 3072 + h];
    int base = b*G4H;
    #pragma unroll
    for (int s=0;s<KSPLIT;s++){
        const float* p = g_part + (size_t)s*(BB*G4H) + base;
        gi += p[h]; gf += p[1024+h]; gg += p[2048+h]; go += p[3072+h];
    }
    float c  = g_c[gid];
    float ii = 1.f/(1.f+expf(-gi));
    float ff = 1.f/(1.f+expf(-gf));
    float oo = 1.f/(1.f+expf(-go));
    float gt = tanhf(gg);
    float cn = ff*c + ii*gt;
    float hn = oo*tanhf(cn);
    g_c[gid] = cn; g_h[gid] = hn;

    __nv_bfloat16 hhi = __float2bfloat16_rn(hn);
    float hif = __bfloat162float(hhi);
    __nv_bfloat16 hlo = __float2bfloat16_rn(hn - hif);
    size_t arow = (size_t)(t*64 + b)*KCAT;
    g_Acat[arow + h]        = hhi;
    g_Acat[arow + 1024 + h] = hhi;
    g_Acat[arow + 2048 + h] = hlo;
}

// ============================================================
// proj_W fp32 -> B' = [Bh | Bl | Bh] (bf16)
// ============================================================
__global__ __launch_bounds__(256)
void conv_w(const float* __restrict__ W)
{
    size_t i = (size_t)blockIdx.x*blockDim.x + threadIdx.x;   // 8,192,000 float4s
    int n = (int)(i >> 8);
    int k = (int)(i & 255) * 4;
    float4 v = ((const float4*)W)[i];
    __nv_bfloat16 h0 = __float2bfloat16_rn(v.x);
    __nv_bfloat16 h1 = __float2bfloat16_rn(v.y);
    __nv_bfloat16 h2 = __float2bfloat16_rn(v.z);
    __nv_bfloat16 h3 = __float2bfloat16_rn(v.w);
    __nv_bfloat16 l0 = __float2bfloat16_rn(v.x - __bfloat162float(h0));
    __nv_bfloat16 l1 = __float2bfloat16_rn(v.y - __bfloat162float(h1));
    __nv_bfloat16 l2 = __float2bfloat16_rn(v.z - __bfloat162float(h2));
    __nv_bfloat16 l3 = __float2bfloat16_rn(v.w - __bfloat162float(h3));
    ull hi, lo;
    asm("mov.b64 %0, {%1,%2,%3,%4};" : "=l"(hi)
        : "h"(*(unsigned short*)&h0), "h"(*(unsigned short*)&h1),
          "h"(*(unsigned short*)&h2), "h"(*(unsigned short*)&h3));
    asm("mov.b64 %0, {%1,%2,%3,%4};" : "=l"(lo)
        : "h"(*(unsigned short*)&l0), "h"(*(unsigned short*)&l1),
          "h"(*(unsigned short*)&l2), "h"(*(unsigned short*)&l3));
    size_t rb = (size_t)n*KCAT;
    *(ull*)(g_Bcat + rb + k)        = hi;
    *(ull*)(g_Bcat + rb + 1024 + k) = lo;
    *(ull*)(g_Bcat + rb + 2048 + k) = hi;
}

// ============================================================
// Projection via mma.sync bf16: out = A'(3200xK) . B'(32000xK)^T + bias
// CTA 128x128, 8 warps (4M x 2N), 3-stage cp.async pipeline, K=3072.
// smem rows padded to 80B -> conflict-free ldmatrix.
// ============================================================
#define NSTG 3
#define TSTAGE 10240            /* 128 rows * 80 B */
#define SM_PROJ (NSTG*2*TSTAGE) /* 61440 */

__global__ __launch_bounds__(256)
void proj_mma(float* __restrict__ out, const float* __restrict__ bias)
{
    extern __shared__ __align__(16) char sm[];
    const uint32_t uA = smem_u32(sm);
    const uint32_t uB = uA + NSTG*TSTAGE;
    const int tid = threadIdx.x;
    const int wid = tid >> 5, lane = tid & 31;
    const int m0 = blockIdx.x * 128;
    const int n0 = blockIdx.y * 128;
    const int wm = wid & 3, wn = wid >> 2;

    const int lrow = tid >> 2;            // 0..63
    const int lc   = (tid & 3);           // 16B chunk in 64B row

    float acc[2][8][4];
    #pragma unroll
    for (int a=0;a<2;a++)
        #pragma unroll
        for (int j=0;j<8;j++)
            #pragma unroll
            for (int x=0;x<4;x++) acc[a][j][x] = 0.f;

    const __nv_bfloat16* gA = g_Acat + (size_t)m0*KCAT;
    const __nv_bfloat16* gB = g_Bcat + (size_t)n0*KCAT;

    // ---- stage loader ----
    auto load_stage = [&](int slot, int ks){
        int k0 = ks * 32;
        #pragma unroll
        for (int half = 0; half < 2; half++){
            int row = lrow + half*64;
            cpasync16(uA + slot*TSTAGE + row*80 + lc*16,
                      gA + (size_t)row*KCAT + k0 + lc*8);
            cpasync16(uB + slot*TSTAGE + row*80 + lc*16,
                      gB + (size_t)row*KCAT + k0 + lc*8);
        }
        cp_commit();
    };

    load_stage(0, 0);
    load_stage(1, 1);

    const int g  = lane >> 3;     // ldmatrix tile group 0..3
    const int lr = lane & 7;

    for (int ks = 0; ks < 96; ks++){
        asm volatile("cp.async.wait_group 1;");
        __syncthreads();
        int ld = ks + NSTG - 1;
        if (ld < 96) load_stage(ld % NSTG, ld);
        else cp_commit();

        const uint32_t bufA = uA + (ks % NSTG)*TSTAGE;
        const uint32_t bufB = uB + (ks % NSTG)*TSTAGE;

        #pragma unroll
        for (int kk = 0; kk < 32; kk += 16){
            uint32_t afr[2][4];
            #pragma unroll
            for (int mi = 0; mi < 2; mi++){
                int row = wm*32 + mi*16 + ((g & 1) ? 8 : 0) + lr;
                int kof = kk + (g >> 1)*8;
                ldm4(afr[mi], bufA + row*80 + kof*2);
            }
            uint32_t bfr[4][4];
            #pragma unroll
            for (int p = 0; p < 4; p++){
                int row = wn*64 + p*16 + (g >> 1)*8 + lr;
                int kof = kk + (g & 1)*8;
                ldm4(bfr[p], bufB + row*80 + kof*2);
            }
            #pragma unroll
            for (int mi = 0; mi < 2; mi++)
                #pragma unroll
                for (int j = 0; j < 8; j++){
                    int p = j >> 1, h2 = (j & 1)*2;
                    mma16816(acc[mi][j], afr[mi], bfr[p][h2], bfr[p][h2+1]);
                }
        }
        __syncthreads();
    }

    // ---- epilogue ----
    const int tm = lane >> 2;
    const int tn = (lane & 3)*2;
    #pragma unroll
    for (int mi = 0; mi < 2; mi++){
        #pragma unroll
        for (int j = 0; j < 8; j++){
            int gn = n0 + wn*64 + j*8 + tn;
            float2 bb = *(const float2*)(bias + gn);
            int gm0 = m0 + wm*32 + mi*16 + tm;
            if (gm0 < MPROJ){
                float2 o; o.x = acc[mi][j][0] + bb.x; o.y = acc[mi][j][1] + bb.y;
                *(float2*)(out + (size_t)gm0*VTS + gn) = o;
            }
            int gm1 = gm0 + 8;
            if (gm1 < MPROJ){
                float2 o; o.x = acc[mi][j][2] + bb.x; o.y = acc[mi][j][3] + bb.y;
                *(float2*)(out + (size_t)gm1*VTS + gn) = o;
            }
        }
    }
}

// ============================================================
extern "C" void kernel_launch(void* const* d_in, const int* in_sizes, int n_in,
                              void* d_out, int out_size)
{
    const int*   src      = (const int*)  d_in[0];
    const int*   pos      = (const int*)  d_in[2];
    const int*   tgt      = (const int*)  d_in[3];
    const float* enc_emb  = (const float*)d_in[4];
    const float* pos_emb  = (const float*)d_in[5];
    const float* cat_W    = (const float*)d_in[6];
    const float* cat_b    = (const float*)d_in[7];
    const float* scale_W  = (const float*)d_in[8];
    const float* scale_b  = (const float*)d_in[9];
    const float* dec_emb  = (const float*)d_in[10];
    const float* attn_W   = (const float*)d_in[11];
    const float* W_ih     = (const float*)d_in[13];
    const float* W_hh     = (const float*)d_in[14];
    const float* b_ih     = (const float*)d_in[15];
    const float* b_hh     = (const float*)d_in[16];
    const float* proj_W   = (const float*)d_in[17];
    const float* proj_b   = (const float*)d_in[18];
    float* out = (float*)d_out;

    cudaFuncSetAttribute(proj_mma, cudaFuncAttributeMaxDynamicSharedMemorySize, SM_PROJ);

    // B' conversion (independent; overlaps encoder work in-order on stream)
    conv_w<<<32000, 256>>>(proj_W);

    // Encoder
    enc_gemm<<<dim3(25,4), 256>>>(src, pos, enc_emb, pos_emb, cat_W, cat_b);
    avg_kernel<<<64, 512>>>();
    h0_kernel<<<256, 256>>>(scale_W, scale_b);

    // Loop-invariant attention context + hoisted per-step constants
    attn_kernel<<<64, 256>>>(attn_W, src);
    gconst_kernel<<<1024, 256>>>(W_ih, b_ih, b_hh);
    dec_pre<<<dim3(25,32), 256>>>(tgt, dec_emb, W_ih);

    // Recurrence: only h . W_hh^T is sequential now (K=1024)
    for (int t = 0; t < NSTEP; t++){
        gates_gemm<<<dim3(32, KSPLIT), 128>>>(W_hh);
        lstm_pw<<<256, 256>>>(t);
    }

    // Tensor-core projection (single GEMM, K=3072 3-term concat)
    proj_mma<<<dim3(25,250), 256, SM_PROJ>>>(out, proj_b);
}